// round 6
// baseline (speedup 1.0000x reference)
#include <cuda_runtime.h>

// WindowAttention3D fused kernel: one CTA per window, 512 threads (R5).
//   B=2048 windows, N=98 tokens, C=128 channels, H=4 heads, hd=32.
// R5: 16 warps/CTA for latency hiding; split-K in QKV/PV/proj; retiled scores.
// SMEM layout (dynamic, 229184 B):
//   qkv [98][388]  (q|k|v; q slot reused for attn output)
//   A   [12936 f]  (x tile [98][132] -> scores [112][112] -> proj_w chunk [64][132])
//   wch [48][132]  (qkv_w chunk staging; proj-partial buffer [98][64])

#define NTOK 98
#define CDIM 128
#define NHEADS 4
#define HD 32
#define QP 388
#define XP 132
#define SP 112
#define WP 132
#define CHUNK 48
#define NTHREADS 512
#define SMEM_FLOATS (NTOK*QP + 12936 + CHUNK*WP)

typedef unsigned long long u64;

__device__ __forceinline__ void fma2(u64& d, u64 a, u64 b) {
    asm("fma.rn.f32x2 %0, %1, %2, %0;" : "+l"(d) : "l"(a), "l"(b));
}
__device__ __forceinline__ float hsum2(u64 v) {
    float a, b;
    asm("mov.b64 {%0, %1}, %2;" : "=f"(a), "=f"(b) : "l"(v));
    return a + b;
}
__device__ __forceinline__ u64 dup2(float s) {
    u64 r;
    asm("mov.b64 %0, {%1, %1};" : "=l"(r) : "f"(s));
    return r;
}

__global__ __launch_bounds__(NTHREADS, 1)
void wa3d_kernel(const float* __restrict__ x,
                 const float* __restrict__ mask,
                 const float* __restrict__ qkv_w,
                 const float* __restrict__ qkv_b,
                 const float* __restrict__ rel,
                 const float* __restrict__ proj_w,
                 const float* __restrict__ proj_b,
                 float* __restrict__ out,
                 int Lmask)
{
    extern __shared__ float sm[];
    float* qkv = sm;                 // NTOK*QP floats
    float* A   = sm + NTOK*QP;       // 12936 floats (union region)
    float* wch = A + 12936;          // CHUNK*WP floats (also proj partials)

    const int tid = threadIdx.x;
    const int b = blockIdx.x;
    const float scale = 0.17677669529663688f;   // 32^-0.5

    // ---------------- load x tile: A = xs[98][132] ----------------
    {
        const float4* xb = (const float4*)(x + (size_t)b * NTOK * CDIM);
        for (int f = tid; f < NTOK*CDIM/4; f += NTHREADS) {
            int row = f >> 5, c4 = f & 31;
            float4 v = xb[f];
            *(float4*)&A[row*XP + c4*4] = v;
        }
    }
    __syncthreads();

    // ---------------- QKV projection (split-K across thread halves) ----------------
    {
        const int zk = tid >> 8;            // 0: k[0..63], 1: k[64..127]
        const int t  = tid & 255;
        const int ty = t >> 4, tx = t & 15;
        int irow[7];
        #pragma unroll
        for (int r = 0; r < 7; r++) irow[r] = min(ty + 16*r, NTOK-1) * XP;

        for (int ch = 0; ch < 8; ch++) {
            const int c0 = ch * CHUNK;
            for (int f = tid; f < CHUNK*CDIM/4; f += NTHREADS) {
                int row = f >> 5, c4 = f & 31;
                float4 v = ((const float4*)(qkv_w + (size_t)(c0 + row)*CDIM))[c4];
                *(float4*)&wch[row*WP + c4*4] = v;
            }
            __syncthreads();

            u64 acc[7][3];
            #pragma unroll
            for (int r = 0; r < 7; r++)
                #pragma unroll
                for (int c = 0; c < 3; c++) acc[r][c] = 0ull;

            const int k40 = zk * 16;
            #pragma unroll 4
            for (int kk = 0; kk < 16; kk++) {
                const int k4 = k40 + kk;
                ulonglong2 wv[3];
                #pragma unroll
                for (int c = 0; c < 3; c++)
                    wv[c] = *(const ulonglong2*)&wch[(tx + 16*c)*WP + k4*4];
                #pragma unroll
                for (int r = 0; r < 7; r++) {
                    ulonglong2 xv = *(const ulonglong2*)&A[irow[r] + k4*4];
                    #pragma unroll
                    for (int c = 0; c < 3; c++) {
                        fma2(acc[r][c], xv.x, wv[c].x);
                        fma2(acc[r][c], xv.y, wv[c].y);
                    }
                }
            }
            // zk==1 stores partial, zk==0 finalizes (+partial +bias, scale for q)
            if (zk == 1) {
                #pragma unroll
                for (int r = 0; r < 7; r++) {
                    int i = ty + 16*r;
                    if (i < NTOK) {
                        #pragma unroll
                        for (int c = 0; c < 3; c++)
                            qkv[i*QP + c0 + tx + 16*c] = hsum2(acc[r][c]);
                    }
                }
            }
            __syncthreads();
            if (zk == 0) {
                #pragma unroll
                for (int r = 0; r < 7; r++) {
                    int i = ty + 16*r;
                    if (i < NTOK) {
                        #pragma unroll
                        for (int c = 0; c < 3; c++) {
                            int col = c0 + tx + 16*c;
                            float v = hsum2(acc[r][c]) + qkv[i*QP + col] + __ldg(&qkv_b[col]);
                            if (col < CDIM) v *= scale;
                            qkv[i*QP + col] = v;
                        }
                    }
                }
            }
            __syncthreads();
        }
    }

    // ---------------- attention ----------------
    float* s = A;                                           // s[112][112]
    const float* maskb = mask + (size_t)(b % Lmask) * NTOK * NTOK;

    // scores mapping: sy (32 row groups) x sx (16 col threads)
    const int sy = tid >> 4, sx = tid & 15;
    int iq[4], jk[7], ai[4], bj[7];
    #pragma unroll
    for (int r = 0; r < 4; r++) {
        int i = min(sy + 32*r, NTOK-1);
        iq[r] = i;
        ai[r] = (i/49)*169 + ((i/7)%7)*13 + (i%7);
    }
    #pragma unroll
    for (int c = 0; c < 7; c++) {
        int j = min(sx + 16*c, NTOK-1);
        jk[c] = j;
        bj[c] = (j/49)*169 + ((j/7)%7)*13 + (j%7);
    }

    for (int h = 0; h < NHEADS; h++) {
        const float* relh = rel + h * 507;

        // --- scores: s[i][j] = q_h[i]·k_h[j] + bias + mask (full K per thread) ---
        {
            u64 acc[4][7];
            #pragma unroll
            for (int r = 0; r < 4; r++)
                #pragma unroll
                for (int c = 0; c < 7; c++) acc[r][c] = 0ull;

            const int qb = h*HD, kb = CDIM + h*HD;
            #pragma unroll
            for (int d4 = 0; d4 < 8; d4++) {
                ulonglong2 kv[7];
                #pragma unroll
                for (int c = 0; c < 7; c++)
                    kv[c] = *(const ulonglong2*)&qkv[jk[c]*QP + kb + d4*4];
                #pragma unroll
                for (int r = 0; r < 4; r++) {
                    ulonglong2 qv = *(const ulonglong2*)&qkv[iq[r]*QP + qb + d4*4];
                    #pragma unroll
                    for (int c = 0; c < 7; c++) {
                        fma2(acc[r][c], qv.x, kv[c].x);
                        fma2(acc[r][c], qv.y, kv[c].y);
                    }
                }
            }
            #pragma unroll
            for (int r = 0; r < 4; r++) {
                int rr = sy + 32*r;
                if (rr < NTOK) {
                    int i = iq[r];
                    #pragma unroll
                    for (int c = 0; c < 7; c++) {
                        int idx = ai[r] - bj[c] + 253;
                        float v = hsum2(acc[r][c]) + __ldg(&relh[idx])
                                + __ldg(&maskb[i*NTOK + jk[c]]);
                        s[rr*SP + (sx + 16*c)] = v;
                    }
                }
            }
        }
        __syncthreads();

        // --- softmax over j (one warp per row, 16 warps) ---
        {
            const int warp = tid >> 5, lane = tid & 31;
            for (int row = warp; row < NTOK; row += 16) {
                float v0 = (lane      < NTOK) ? s[row*SP + lane     ] : -1e30f;
                float v1 = (lane + 32 < NTOK) ? s[row*SP + lane + 32] : -1e30f;
                float v2 = (lane + 64 < NTOK) ? s[row*SP + lane + 64] : -1e30f;
                float v3 = (lane + 96 < NTOK) ? s[row*SP + lane + 96] : -1e30f;
                float m = fmaxf(fmaxf(v0, v1), fmaxf(v2, v3));
                #pragma unroll
                for (int o = 16; o > 0; o >>= 1)
                    m = fmaxf(m, __shfl_xor_sync(0xffffffffu, m, o));
                v0 = __expf(v0 - m); v1 = __expf(v1 - m);
                v2 = __expf(v2 - m); v3 = __expf(v3 - m);
                float sum = v0 + v1 + v2 + v3;
                #pragma unroll
                for (int o = 16; o > 0; o >>= 1)
                    sum += __shfl_xor_sync(0xffffffffu, sum, o);
                float inv = 1.0f / sum;
                if (lane      < NTOK) s[row*SP + lane     ] = v0*inv;
                if (lane + 32 < NTOK) s[row*SP + lane + 32] = v1*inv;
                if (lane + 64 < NTOK) s[row*SP + lane + 64] = v2*inv;
                if (lane + 96 < NTOK) s[row*SP + lane + 96] = v3*inv;
            }
        }
        __syncthreads();

        // --- o_h = P @ v_h (split-K over tokens), into dead q_h slot ---
        {
            const int px = tid & 7;             // 8 col groups * 4 floats = 32 cols
            const int py = (tid >> 3) & 31;     // 32 row groups
            const int pz = tid >> 8;            // token split: [0..48] / [49..97]
            int ir[4];
            #pragma unroll
            for (int r = 0; r < 4; r++) ir[r] = min(py + 32*r, NTOK-1) * SP;
            const int vb = 2*CDIM + h*HD + px*4;

            u64 acc0[4], acc1[4];
            #pragma unroll
            for (int r = 0; r < 4; r++) { acc0[r] = 0ull; acc1[r] = 0ull; }

            const int k0 = pz * 49;
            #pragma unroll 2
            for (int kk = 0; kk < 49; kk++) {
                const int k = k0 + kk;
                ulonglong2 vv = *(const ulonglong2*)&qkv[k*QP + vb];
                #pragma unroll
                for (int r = 0; r < 4; r++) {
                    u64 sp = dup2(s[ir[r] + k]);
                    fma2(acc0[r], sp, vv.x);
                    fma2(acc1[r], sp, vv.y);
                }
            }
            if (pz == 1) {
                #pragma unroll
                for (int r = 0; r < 4; r++) {
                    int i = py + 32*r;
                    if (i < NTOK) {
                        ulonglong2 o2; o2.x = acc0[r]; o2.y = acc1[r];
                        *(ulonglong2*)&qkv[i*QP + h*HD + px*4] = o2;
                    }
                }
            }
            __syncthreads();
            if (pz == 0) {
                #pragma unroll
                for (int r = 0; r < 4; r++) {
                    int i = py + 32*r;
                    if (i < NTOK) {
                        ulonglong2 p2 = *(const ulonglong2*)&qkv[i*QP + h*HD + px*4];
                        fma2(acc0[r], p2.x, dup2(0.f));   // no-op pattern avoided below
                        ulonglong2 o2;
                        // combine: own acc + partial (elementwise fp32 adds)
                        {
                            float a0, a1, b0, b1;
                            asm("mov.b64 {%0, %1}, %2;" : "=f"(a0), "=f"(a1) : "l"(acc0[r]));
                            asm("mov.b64 {%0, %1}, %2;" : "=f"(b0), "=f"(b1) : "l"(p2.x));
                            asm("mov.b64 %0, {%1, %2};" : "=l"(o2.x) : "f"(a0+b0), "f"(a1+b1));
                            asm("mov.b64 {%0, %1}, %2;" : "=f"(a0), "=f"(a1) : "l"(acc1[r]));
                            asm("mov.b64 {%0, %1}, %2;" : "=f"(b0), "=f"(b1) : "l"(p2.y));
                            asm("mov.b64 %0, {%1, %2};" : "=l"(o2.y) : "f"(a0+b0), "f"(a1+b1));
                        }
                        *(ulonglong2*)&qkv[i*QP + h*HD + px*4] = o2;
                    }
                }
            }
            __syncthreads();
        }
    }

    // ---------------- output projection (split-K across thread halves) ----------------
    {
        const int zk = tid >> 8;
        const int t  = tid & 255;
        const int ty = t >> 4, tx = t & 15;
        float* pw = A;                                      // proj_w chunk [64][132]
        float* part = wch;                                  // partials [98][64]
        int irow[7];
        #pragma unroll
        for (int r = 0; r < 7; r++) irow[r] = min(ty + 16*r, NTOK-1) * QP;

        for (int ch = 0; ch < 2; ch++) {
            const int c0 = ch * 64;
            for (int f = tid; f < 64*CDIM/4; f += NTHREADS) {
                int row = f >> 5, c4 = f & 31;
                float4 v = ((const float4*)(proj_w + (size_t)(c0 + row)*CDIM))[c4];
                *(float4*)&pw[row*WP + c4*4] = v;
            }
            __syncthreads();

            u64 acc[7][4];
            #pragma unroll
            for (int r = 0; r < 7; r++)
                #pragma unroll
                for (int c = 0; c < 4; c++) acc[r][c] = 0ull;

            const int k40 = zk * 16;
            #pragma unroll 4
            for (int kk = 0; kk < 16; kk++) {
                const int k4 = k40 + kk;
                ulonglong2 wv[4];
                #pragma unroll
                for (int c = 0; c < 4; c++)
                    wv[c] = *(const ulonglong2*)&pw[(tx + 16*c)*WP + k4*4];
                #pragma unroll
                for (int r = 0; r < 7; r++) {
                    ulonglong2 ov = *(const ulonglong2*)&qkv[irow[r] + k4*4];
                    #pragma unroll
                    for (int c = 0; c < 4; c++) {
                        fma2(acc[r][c], ov.x, wv[c].x);
                        fma2(acc[r][c], ov.y, wv[c].y);
                    }
                }
            }
            if (zk == 1) {
                #pragma unroll
                for (int r = 0; r < 7; r++) {
                    int i = ty + 16*r;
                    if (i < NTOK) {
                        #pragma unroll
                        for (int c = 0; c < 4; c++)
                            part[i*64 + tx + 16*c] = hsum2(acc[r][c]);
                    }
                }
            }
            __syncthreads();
            if (zk == 0) {
                #pragma unroll
                for (int r = 0; r < 7; r++) {
                    int i = ty + 16*r;
                    if (i < NTOK) {
                        #pragma unroll
                        for (int c = 0; c < 4; c++) {
                            int col = c0 + tx + 16*c;
                            out[(size_t)b*NTOK*CDIM + i*CDIM + col] =
                                hsum2(acc[r][c]) + part[i*64 + tx + 16*c] + __ldg(&proj_b[col]);
                        }
                    }
                }
            }
            __syncthreads();
        }
    }
}

extern "C" void kernel_launch(void* const* d_in, const int* in_sizes, int n_in,
                              void* d_out, int out_size)
{
    const float* x      = (const float*)d_in[0];
    const float* mask   = (const float*)d_in[1];
    const float* qkv_w  = (const float*)d_in[2];
    const float* qkv_b  = (const float*)d_in[3];
    const float* rel    = (const float*)d_in[4];
    const float* proj_w = (const float*)d_in[5];
    const float* proj_b = (const float*)d_in[6];

    const int B = in_sizes[0] / (NTOK * CDIM);          // 2048
    const int L = in_sizes[1] / (NTOK * NTOK);          // 512

    const size_t smem_bytes = (size_t)SMEM_FLOATS * sizeof(float);   // 229184
    cudaFuncSetAttribute(wa3d_kernel,
                         cudaFuncAttributeMaxDynamicSharedMemorySize,
                         (int)smem_bytes);

    wa3d_kernel<<<B, NTHREADS, smem_bytes>>>(x, mask, qkv_w, qkv_b, rel,
                                             proj_w, proj_b, (float*)d_out, L);
}

// round 7
// speedup vs baseline: 1.3543x; 1.3543x over previous
#include <cuda_runtime.h>
#include <cuda_bf16.h>
#include <stdint.h>

// WindowAttention3D fused kernel: one CTA per window, 512 threads (R6).
//   B=2048 windows, N=98 tokens, C=128 channels, H=4 heads, hd=32.
// R6: QKV + output projection on tensor cores (mma.sync m16n8k16 bf16,
//     3-term hi/lo split for fp32-class precision). Scores/softmax/PV SIMT.
// SMEM (bytes, total 222816):
//   [0      ) qkv   [98][388] f32   (q|k|v; q slot reused for attn output)
//   [152096 ) XHI   [98][136] bf16  (x or attn-out hi; aliased by scores s[112][112])
//   [178752 ) XLO   [98][136] bf16  (lo part)
//   [205408 ) WHI   [32][136] bf16  (weight chunk hi)
//   [214112 ) WLO   [32][136] bf16  (weight chunk lo)

#define NTOK 98
#define CDIM 128
#define NHEADS 4
#define HD 32
#define QP 388
#define SP 112
#define NTHREADS 512
#define BPITCH 272           // bf16 row pitch in BYTES (136 elems)
#define OFF_QKV 0
#define OFF_XHI 152096
#define OFF_XLO 178752
#define OFF_WHI 205408
#define OFF_WLO 214112
#define SMEM_BYTES 222816

typedef unsigned long long u64;

// ---------- fp32x2 packed FMA helpers (SIMT phases) ----------
__device__ __forceinline__ void fma2(u64& d, u64 a, u64 b) {
    asm("fma.rn.f32x2 %0, %1, %2, %0;" : "+l"(d) : "l"(a), "l"(b));
}
__device__ __forceinline__ float hsum2(u64 v) {
    float a, b;
    asm("mov.b64 {%0, %1}, %2;" : "=f"(a), "=f"(b) : "l"(v));
    return a + b;
}
__device__ __forceinline__ u64 dup2(float s) {
    u64 r;
    asm("mov.b64 %0, {%1, %1};" : "=l"(r) : "f"(s));
    return r;
}

// ---------- tensor-core helpers ----------
__device__ __forceinline__ uint32_t smem_u32(const void* p) {
    uint32_t a;
    asm("{ .reg .u64 t; cvta.to.shared.u64 t, %1; cvt.u32.u64 %0, t; }"
        : "=r"(a) : "l"(p));
    return a;
}
__device__ __forceinline__ void ldsm4(uint32_t* r, uint32_t a) {
    asm volatile("ldmatrix.sync.aligned.m8n8.x4.shared.b16 {%0,%1,%2,%3}, [%4];"
        : "=r"(r[0]), "=r"(r[1]), "=r"(r[2]), "=r"(r[3]) : "r"(a));
}
__device__ __forceinline__ void mma16816(float* c, const uint32_t* a,
                                         uint32_t b0, uint32_t b1) {
    asm volatile("mma.sync.aligned.m16n8k16.row.col.f32.bf16.bf16.f32 "
        "{%0,%1,%2,%3}, {%4,%5,%6,%7}, {%8,%9}, {%0,%1,%2,%3};"
        : "+f"(c[0]), "+f"(c[1]), "+f"(c[2]), "+f"(c[3])
        : "r"(a[0]), "r"(a[1]), "r"(a[2]), "r"(a[3]), "r"(b0), "r"(b1));
}
__device__ __forceinline__ uint32_t packbf(__nv_bfloat16 a, __nv_bfloat16 b) {
    __nv_bfloat162 t(a, b);              // x = a (low), y = b (high)
    return *(uint32_t*)&t;
}
// split one float4 into bf16 hi/lo pairs (2-term: a = hi + lo, err ~2^-16)
__device__ __forceinline__ void split4(float4 v, uint2& hi, uint2& lo) {
    __nv_bfloat16 h0 = __float2bfloat16(v.x), h1 = __float2bfloat16(v.y),
                  h2 = __float2bfloat16(v.z), h3 = __float2bfloat16(v.w);
    __nv_bfloat16 l0 = __float2bfloat16(v.x - __bfloat162float(h0)),
                  l1 = __float2bfloat16(v.y - __bfloat162float(h1)),
                  l2 = __float2bfloat16(v.z - __bfloat162float(h2)),
                  l3 = __float2bfloat16(v.w - __bfloat162float(h3));
    hi.x = packbf(h0, h1); hi.y = packbf(h2, h3);
    lo.x = packbf(l0, l1); lo.y = packbf(l2, l3);
}

__global__ __launch_bounds__(NTHREADS, 1)
void wa3d_kernel(const float* __restrict__ x,
                 const float* __restrict__ mask,
                 const float* __restrict__ qkv_w,
                 const float* __restrict__ qkv_b,
                 const float* __restrict__ rel,
                 const float* __restrict__ proj_w,
                 const float* __restrict__ proj_b,
                 float* __restrict__ out,
                 int Lmask)
{
    extern __shared__ char smc[];
    float* qkv = (float*)(smc + OFF_QKV);
    float* s   = (float*)(smc + OFF_XHI);      // scores alias XHI/XLO region

    const uint32_t sbase = smem_u32(smc);
    const uint32_t XHI = sbase + OFF_XHI, XLO = sbase + OFF_XLO;
    const uint32_t WHI = sbase + OFF_WHI, WLO = sbase + OFF_WLO;

    const int tid  = threadIdx.x;
    const int warp = tid >> 5, lane = tid & 31;
    const int b = blockIdx.x;
    const float scale = 0.17677669529663688f;   // 32^-0.5

    // mma tile mapping: warps 0..13 -> (m-tile mi, n-half nh)
    const int mi = warp >> 1, nh = warp & 1;
    // ldmatrix lane addressing (A: 16x16 from row-major; B: 2 n-tiles 16x16 [n][k])
    const int arow = min(mi*16 + (lane & 7) + ((lane >> 3) & 1)*8, NTOK-1);
    const uint32_t aoff = (uint32_t)arow*BPITCH + ((lane >> 4) & 1)*16;
    const int brow = (lane & 7) + ((lane >> 4) & 1)*8 + nh*16;
    const uint32_t boff = (uint32_t)brow*BPITCH + ((lane >> 3) & 1)*16;
    const int g = lane >> 2, tg = lane & 3;

    // ---------------- x -> bf16 hi/lo tiles ----------------
    {
        const float4* xb = (const float4*)(x + (size_t)b * NTOK * CDIM);
        for (int f = tid; f < NTOK*CDIM/4; f += NTHREADS) {
            int row = f >> 5, c4 = f & 31;
            uint2 hi, lo; split4(xb[f], hi, lo);
            *(uint2*)(smc + OFF_XHI + row*BPITCH + c4*8) = hi;
            *(uint2*)(smc + OFF_XLO + row*BPITCH + c4*8) = lo;
        }
    }
    __syncthreads();

    // ---------------- QKV projection on tensor cores ----------------
    {
        uint32_t Ahi[8][4], Alo[8][4];
        if (warp < 14) {
            #pragma unroll
            for (int kk = 0; kk < 8; kk++) {
                ldsm4(Ahi[kk], XHI + aoff + kk*32);
                ldsm4(Alo[kk], XLO + aoff + kk*32);
            }
        }
        for (int ch = 0; ch < 12; ch++) {
            const int c0 = ch * 32;
            // stage weight chunk (32 out-cols x 128 k) as bf16 hi/lo
            for (int f = tid; f < 32*CDIM/4; f += NTHREADS) {
                int row = f >> 5, c4 = f & 31;
                float4 v = *(const float4*)(qkv_w + (size_t)(c0 + row)*CDIM + c4*4);
                uint2 hi, lo; split4(v, hi, lo);
                *(uint2*)(smc + OFF_WHI + row*BPITCH + c4*8) = hi;
                *(uint2*)(smc + OFF_WLO + row*BPITCH + c4*8) = lo;
            }
            __syncthreads();
            if (warp < 14) {
                float acc[2][4] = {{0,0,0,0},{0,0,0,0}};
                #pragma unroll
                for (int kk = 0; kk < 8; kk++) {
                    uint32_t bh[4], bl[4];
                    ldsm4(bh, WHI + boff + kk*32);
                    ldsm4(bl, WLO + boff + kk*32);
                    mma16816(acc[0], Ahi[kk], bh[0], bh[1]);
                    mma16816(acc[0], Alo[kk], bh[0], bh[1]);
                    mma16816(acc[0], Ahi[kk], bl[0], bl[1]);
                    mma16816(acc[1], Ahi[kk], bh[2], bh[3]);
                    mma16816(acc[1], Alo[kk], bh[2], bh[3]);
                    mma16816(acc[1], Ahi[kk], bl[2], bl[3]);
                }
                const float sc = (c0 < CDIM) ? scale : 1.0f;   // q cols get scale
                const int row0 = mi*16 + g;
                #pragma unroll
                for (int t = 0; t < 2; t++) {
                    int col = c0 + nh*16 + t*8 + tg*2;
                    float b0 = __ldg(qkv_b + col), b1 = __ldg(qkv_b + col + 1);
                    if (row0 < NTOK) {
                        float2 v; v.x = (acc[t][0] + b0)*sc; v.y = (acc[t][1] + b1)*sc;
                        *(float2*)&qkv[row0*QP + col] = v;
                    }
                    if (row0 + 8 < NTOK) {
                        float2 v; v.x = (acc[t][2] + b0)*sc; v.y = (acc[t][3] + b1)*sc;
                        *(float2*)&qkv[(row0+8)*QP + col] = v;
                    }
                }
            }
            __syncthreads();
        }
    }

    // ---------------- attention (SIMT fp32, FFMA2) ----------------
    const float* maskb = mask + (size_t)(b % Lmask) * NTOK * NTOK;

    const int sy = tid >> 4, sx = tid & 15;
    int iq[4], jk[7], ai[4], bj[7];
    #pragma unroll
    for (int r = 0; r < 4; r++) {
        int i = min(sy + 32*r, NTOK-1);
        iq[r] = i;
        ai[r] = (i/49)*169 + ((i/7)%7)*13 + (i%7);
    }
    #pragma unroll
    for (int c = 0; c < 7; c++) {
        int j = min(sx + 16*c, NTOK-1);
        jk[c] = j;
        bj[c] = (j/49)*169 + ((j/7)%7)*13 + (j%7);
    }

    for (int h = 0; h < NHEADS; h++) {
        const float* relh = rel + h * 507;

        // --- scores ---
        {
            u64 acc[4][7];
            #pragma unroll
            for (int r = 0; r < 4; r++)
                #pragma unroll
                for (int c = 0; c < 7; c++) acc[r][c] = 0ull;

            const int qb = h*HD, kb = CDIM + h*HD;
            #pragma unroll
            for (int d4 = 0; d4 < 8; d4++) {
                ulonglong2 kv[7];
                #pragma unroll
                for (int c = 0; c < 7; c++)
                    kv[c] = *(const ulonglong2*)&qkv[jk[c]*QP + kb + d4*4];
                #pragma unroll
                for (int r = 0; r < 4; r++) {
                    ulonglong2 qv = *(const ulonglong2*)&qkv[iq[r]*QP + qb + d4*4];
                    #pragma unroll
                    for (int c = 0; c < 7; c++) {
                        fma2(acc[r][c], qv.x, kv[c].x);
                        fma2(acc[r][c], qv.y, kv[c].y);
                    }
                }
            }
            #pragma unroll
            for (int r = 0; r < 4; r++) {
                int rr = sy + 32*r;
                if (rr < NTOK) {
                    int i = iq[r];
                    #pragma unroll
                    for (int c = 0; c < 7; c++) {
                        int idx = ai[r] - bj[c] + 253;
                        float v = hsum2(acc[r][c]) + __ldg(&relh[idx])
                                + __ldg(&maskb[i*NTOK + jk[c]]);
                        s[rr*SP + (sx + 16*c)] = v;
                    }
                }
            }
        }
        __syncthreads();

        // --- softmax over j (one warp per row, 16 warps) ---
        {
            for (int row = warp; row < NTOK; row += 16) {
                float v0 = (lane      < NTOK) ? s[row*SP + lane     ] : -1e30f;
                float v1 = (lane + 32 < NTOK) ? s[row*SP + lane + 32] : -1e30f;
                float v2 = (lane + 64 < NTOK) ? s[row*SP + lane + 64] : -1e30f;
                float v3 = (lane + 96 < NTOK) ? s[row*SP + lane + 96] : -1e30f;
                float m = fmaxf(fmaxf(v0, v1), fmaxf(v2, v3));
                #pragma unroll
                for (int o = 16; o > 0; o >>= 1)
                    m = fmaxf(m, __shfl_xor_sync(0xffffffffu, m, o));
                v0 = __expf(v0 - m); v1 = __expf(v1 - m);
                v2 = __expf(v2 - m); v3 = __expf(v3 - m);
                float sum = v0 + v1 + v2 + v3;
                #pragma unroll
                for (int o = 16; o > 0; o >>= 1)
                    sum += __shfl_xor_sync(0xffffffffu, sum, o);
                float inv = 1.0f / sum;
                if (lane      < NTOK) s[row*SP + lane     ] = v0*inv;
                if (lane + 32 < NTOK) s[row*SP + lane + 32] = v1*inv;
                if (lane + 64 < NTOK) s[row*SP + lane + 64] = v2*inv;
                if (lane + 96 < NTOK) s[row*SP + lane + 96] = v3*inv;
            }
        }
        __syncthreads();

        // --- o_h = P @ v_h (split-K over tokens), into dead q_h slot ---
        {
            const int px = tid & 7;
            const int py = (tid >> 3) & 31;
            const int pz = tid >> 8;
            int ir[4];
            #pragma unroll
            for (int r = 0; r < 4; r++) ir[r] = min(py + 32*r, NTOK-1) * SP;
            const int vb = 2*CDIM + h*HD + px*4;

            u64 acc0[4], acc1[4];
            #pragma unroll
            for (int r = 0; r < 4; r++) { acc0[r] = 0ull; acc1[r] = 0ull; }

            const int k0 = pz * 49;
            #pragma unroll 2
            for (int kk = 0; kk < 49; kk++) {
                const int k = k0 + kk;
                ulonglong2 vv = *(const ulonglong2*)&qkv[k*QP + vb];
                #pragma unroll
                for (int r = 0; r < 4; r++) {
                    u64 sp = dup2(s[ir[r] + k]);
                    fma2(acc0[r], sp, vv.x);
                    fma2(acc1[r], sp, vv.y);
                }
            }
            if (pz == 1) {
                #pragma unroll
                for (int r = 0; r < 4; r++) {
                    int i = py + 32*r;
                    if (i < NTOK) {
                        ulonglong2 o2; o2.x = acc0[r]; o2.y = acc1[r];
                        *(ulonglong2*)&qkv[i*QP + h*HD + px*4] = o2;
                    }
                }
            }
            __syncthreads();
            if (pz == 0) {
                #pragma unroll
                for (int r = 0; r < 4; r++) {
                    int i = py + 32*r;
                    if (i < NTOK) {
                        ulonglong2 p2 = *(const ulonglong2*)&qkv[i*QP + h*HD + px*4];
                        ulonglong2 o2;
                        float a0, a1, b0, b1;
                        asm("mov.b64 {%0, %1}, %2;" : "=f"(a0), "=f"(a1) : "l"(acc0[r]));
                        asm("mov.b64 {%0, %1}, %2;" : "=f"(b0), "=f"(b1) : "l"(p2.x));
                        asm("mov.b64 %0, {%1, %2};" : "=l"(o2.x) : "f"(a0+b0), "f"(a1+b1));
                        asm("mov.b64 {%0, %1}, %2;" : "=f"(a0), "=f"(a1) : "l"(acc1[r]));
                        asm("mov.b64 {%0, %1}, %2;" : "=f"(b0), "=f"(b1) : "l"(p2.y));
                        asm("mov.b64 %0, {%1, %2};" : "=l"(o2.y) : "f"(a0+b0), "f"(a1+b1));
                        *(ulonglong2*)&qkv[i*QP + h*HD + px*4] = o2;
                    }
                }
            }
            __syncthreads();
        }
    }

    // ---------------- output projection on tensor cores ----------------
    {
        // convert attn-out (qkv cols 0..127) -> bf16 hi/lo tiles (scores dead)
        for (int f = tid; f < NTOK*CDIM/4; f += NTHREADS) {
            int row = f >> 5, c4 = f & 31;
            float4 v = *(const float4*)&qkv[row*QP + c4*4];
            uint2 hi, lo; split4(v, hi, lo);
            *(uint2*)(smc + OFF_XHI + row*BPITCH + c4*8) = hi;
            *(uint2*)(smc + OFF_XLO + row*BPITCH + c4*8) = lo;
        }
        __syncthreads();

        uint32_t Ahi[8][4], Alo[8][4];
        if (warp < 14) {
            #pragma unroll
            for (int kk = 0; kk < 8; kk++) {
                ldsm4(Ahi[kk], XHI + aoff + kk*32);
                ldsm4(Alo[kk], XLO + aoff + kk*32);
            }
        }
        float* outg = out + (size_t)b * NTOK * CDIM;
        for (int ch = 0; ch < 4; ch++) {
            const int c0 = ch * 32;
            for (int f = tid; f < 32*CDIM/4; f += NTHREADS) {
                int row = f >> 5, c4 = f & 31;
                float4 v = *(const float4*)(proj_w + (size_t)(c0 + row)*CDIM + c4*4);
                uint2 hi, lo; split4(v, hi, lo);
                *(uint2*)(smc + OFF_WHI + row*BPITCH + c4*8) = hi;
                *(uint2*)(smc + OFF_WLO + row*BPITCH + c4*8) = lo;
            }
            __syncthreads();
            if (warp < 14) {
                float acc[2][4] = {{0,0,0,0},{0,0,0,0}};
                #pragma unroll
                for (int kk = 0; kk < 8; kk++) {
                    uint32_t bh[4], bl[4];
                    ldsm4(bh, WHI + boff + kk*32);
                    ldsm4(bl, WLO + boff + kk*32);
                    mma16816(acc[0], Ahi[kk], bh[0], bh[1]);
                    mma16816(acc[0], Alo[kk], bh[0], bh[1]);
                    mma16816(acc[0], Ahi[kk], bl[0], bl[1]);
                    mma16816(acc[1], Ahi[kk], bh[2], bh[3]);
                    mma16816(acc[1], Alo[kk], bh[2], bh[3]);
                    mma16816(acc[1], Ahi[kk], bl[2], bl[3]);
                }
                const int row0 = mi*16 + g;
                #pragma unroll
                for (int t = 0; t < 2; t++) {
                    int col = c0 + nh*16 + t*8 + tg*2;
                    float b0 = __ldg(proj_b + col), b1 = __ldg(proj_b + col + 1);
                    if (row0 < NTOK) {
                        float2 v; v.x = acc[t][0] + b0; v.y = acc[t][1] + b1;
                        *(float2*)&outg[row0*CDIM + col] = v;
                    }
                    if (row0 + 8 < NTOK) {
                        float2 v; v.x = acc[t][2] + b0; v.y = acc[t][3] + b1;
                        *(float2*)&outg[(row0+8)*CDIM + col] = v;
                    }
                }
            }
            __syncthreads();
        }
    }
}

extern "C" void kernel_launch(void* const* d_in, const int* in_sizes, int n_in,
                              void* d_out, int out_size)
{
    const float* x      = (const float*)d_in[0];
    const float* mask   = (const float*)d_in[1];
    const float* qkv_w  = (const float*)d_in[2];
    const float* qkv_b  = (const float*)d_in[3];
    const float* rel    = (const float*)d_in[4];
    const float* proj_w = (const float*)d_in[5];
    const float* proj_b = (const float*)d_in[6];

    const int B = in_sizes[0] / (NTOK * CDIM);          // 2048
    const int L = in_sizes[1] / (NTOK * NTOK);          // 512

    cudaFuncSetAttribute(wa3d_kernel,
                         cudaFuncAttributeMaxDynamicSharedMemorySize,
                         SMEM_BYTES);

    wa3d_kernel<<<B, NTHREADS, SMEM_BYTES>>>(x, mask, qkv_w, qkv_b, rel,
                                             proj_w, proj_b, (float*)d_out, L);
}

// round 8
// speedup vs baseline: 1.5436x; 1.1398x over previous
#include <cuda_runtime.h>
#include <cuda_bf16.h>
#include <stdint.h>

// WindowAttention3D fused kernel: one CTA per window, 512 threads (R7).
//   B=2048 windows, N=98 tokens, C=128 channels, H=4 heads, hd=32.
// R7: ALL matmuls on tensor cores (mma.sync m16n8k16 bf16).
//   QKV/proj: 3-term hi/lo split (fp32-class). Scores: plain bf16 (softmax
//   washes absolute logit error). PV: 3-term hi/lo on P and V.
// SMEM (bytes, total 216672):
//   [0     ) QKhi [98][264] bf16 (q cols 0..127 scaled, k cols 128..255)
//   [51744 ) VThi [128][120] bf16 (V transposed: [dim][token]); VTlo at +30720
//   [113184) s    [112][112] f32 scores; softmax rewrites rows in place as
//            packed Phi[112 bf16]|Plo[112 bf16] per 448-B row
//            (also aliased: W-chunk staging for QKV/proj GEMMs)
//   [163360) Ohi  [98][136] bf16; Olo at +26656
//            (also aliased: XHI/XLO input tiles during QKV GEMM)

#define NTOK 98
#define CDIM 128
#define NHEADS 4
#define NTHREADS 512
#define QKP 528          // QKhi row pitch bytes (264 bf16)
#define VTP 240          // VT row pitch bytes (120 bf16)
#define SROW 448         // s row pitch bytes (112 f32)
#define OP2 272          // Ohi/XHI row pitch bytes (136 bf16)
#define OFF_QK 0
#define OFF_VT 51744
#define VTLO_D 30720
#define OFF_S 113184
#define OFF_W OFF_S
#define OFF_WLO (OFF_S + 8704)
#define OFF_O 163360
#define OFF_OLO (OFF_O + 26656)
#define SMEM_BYTES 216672

__device__ __forceinline__ uint32_t smem_u32(const void* p) {
    uint32_t a;
    asm("{ .reg .u64 t; cvta.to.shared.u64 t, %1; cvt.u32.u64 %0, t; }"
        : "=r"(a) : "l"(p));
    return a;
}
__device__ __forceinline__ void ldsm4(uint32_t* r, uint32_t a) {
    asm volatile("ldmatrix.sync.aligned.m8n8.x4.shared.b16 {%0,%1,%2,%3}, [%4];"
        : "=r"(r[0]), "=r"(r[1]), "=r"(r[2]), "=r"(r[3]) : "r"(a));
}
__device__ __forceinline__ void mma16816(float* c, const uint32_t* a,
                                         uint32_t b0, uint32_t b1) {
    asm volatile("mma.sync.aligned.m16n8k16.row.col.f32.bf16.bf16.f32 "
        "{%0,%1,%2,%3}, {%4,%5,%6,%7}, {%8,%9}, {%0,%1,%2,%3};"
        : "+f"(c[0]), "+f"(c[1]), "+f"(c[2]), "+f"(c[3])
        : "r"(a[0]), "r"(a[1]), "r"(a[2]), "r"(a[3]), "r"(b0), "r"(b1));
}
__device__ __forceinline__ uint32_t packbf(float a, float b) {
    __nv_bfloat162 t(__float2bfloat16(a), __float2bfloat16(b));
    return *(uint32_t*)&t;
}
__device__ __forceinline__ void split4(float4 v, uint2& hi, uint2& lo) {
    __nv_bfloat16 h0 = __float2bfloat16(v.x), h1 = __float2bfloat16(v.y),
                  h2 = __float2bfloat16(v.z), h3 = __float2bfloat16(v.w);
    float l0 = v.x - __bfloat162float(h0), l1 = v.y - __bfloat162float(h1),
          l2 = v.z - __bfloat162float(h2), l3 = v.w - __bfloat162float(h3);
    __nv_bfloat162 hx(h0, h1), hy(h2, h3);
    hi.x = *(uint32_t*)&hx; hi.y = *(uint32_t*)&hy;
    lo.x = packbf(l0, l1);  lo.y = packbf(l2, l3);
}
__device__ __forceinline__ int airel(int i) {      // linearized rel-pos key
    return (i/49)*169 + ((i/7)%7)*13 + (i%7);
}

__global__ __launch_bounds__(NTHREADS, 1)
void wa3d_kernel(const float* __restrict__ x,
                 const float* __restrict__ mask,
                 const float* __restrict__ qkv_w,
                 const float* __restrict__ qkv_b,
                 const float* __restrict__ rel,
                 const float* __restrict__ proj_w,
                 const float* __restrict__ proj_b,
                 float* __restrict__ out,
                 int Lmask)
{
    extern __shared__ char smc[];
    const uint32_t sb = smem_u32(smc);
    float* s = (float*)(smc + OFF_S);

    const int tid  = threadIdx.x;
    const int warp = tid >> 5, lane = tid & 31;
    const int b = blockIdx.x;
    const float scale = 0.17677669529663688f;

    // warp-tile mapping shared by all MMA phases
    const int mi = warp >> 1, nh = warp & 1;
    const int g = lane >> 2, tg = lane & 3;
    const int r0 = mi*16 + g, r1 = r0 + 8;
    // A-operand lane map (row-major): bit3 -> row+8, bit4 -> k-half
    const int rbA = (lane & 7) + ((lane >> 3) & 1)*8;
    const uint32_t cbA = ((lane >> 4) & 1)*16;
    const int arowA = min(mi*16 + rbA, NTOK-1);
    const uint32_t aoff272 = (uint32_t)arowA*OP2 + cbA;
    // B-operand lane map ([n][k] row-major): bit4 -> n+8, bit3 -> k-half
    const int rbB = (lane & 7) + ((lane >> 4) & 1)*8;
    const uint32_t cbB = ((lane >> 3) & 1)*16;
    const uint32_t boffW = (uint32_t)((rbB + nh*16)*OP2) + cbB;

    // ---------------- 1. x -> bf16 hi/lo tiles (at O region) ----------------
    {
        const float4* xb = (const float4*)(x + (size_t)b * NTOK * CDIM);
        for (int f = tid; f < NTOK*CDIM/4; f += NTHREADS) {
            int row = f >> 5, c4 = f & 31;
            uint2 hi, lo; split4(xb[f], hi, lo);
            *(uint2*)(smc + OFF_O   + row*OP2 + c4*8) = hi;
            *(uint2*)(smc + OFF_OLO + row*OP2 + c4*8) = lo;
        }
    }
    __syncthreads();

    // ---------------- 2. QKV projection (tensor cores, 3-term) ----------------
    {
        uint32_t Ahi[8][4], Alo[8][4];
        if (warp < 14) {
            #pragma unroll
            for (int kk = 0; kk < 8; kk++) {
                ldsm4(Ahi[kk], sb + OFF_O   + aoff272 + kk*32);
                ldsm4(Alo[kk], sb + OFF_OLO + aoff272 + kk*32);
            }
        }
        for (int ch = 0; ch < 12; ch++) {
            const int c0 = ch * 32;
            for (int f = tid; f < 32*CDIM/4; f += NTHREADS) {
                int row = f >> 5, c4 = f & 31;
                float4 v = *(const float4*)(qkv_w + (size_t)(c0 + row)*CDIM + c4*4);
                uint2 hi, lo; split4(v, hi, lo);
                *(uint2*)(smc + OFF_W   + row*OP2 + c4*8) = hi;
                *(uint2*)(smc + OFF_WLO + row*OP2 + c4*8) = lo;
            }
            __syncthreads();
            if (warp < 14) {
                float acc[2][4] = {{0,0,0,0},{0,0,0,0}};
                #pragma unroll
                for (int kk = 0; kk < 8; kk++) {
                    uint32_t bh[4], bl[4];
                    ldsm4(bh, sb + OFF_W   + boffW + kk*32);
                    ldsm4(bl, sb + OFF_WLO + boffW + kk*32);
                    mma16816(acc[0], Ahi[kk], bh[0], bh[1]);
                    mma16816(acc[0], Alo[kk], bh[0], bh[1]);
                    mma16816(acc[0], Ahi[kk], bl[0], bl[1]);
                    mma16816(acc[1], Ahi[kk], bh[2], bh[3]);
                    mma16816(acc[1], Alo[kk], bh[2], bh[3]);
                    mma16816(acc[1], Ahi[kk], bl[2], bl[3]);
                }
                const int ctype = c0 >> 7;              // 0:q 1:k 2:v
                #pragma unroll
                for (int t = 0; t < 2; t++) {
                    const int col = c0 + nh*16 + t*8 + tg*2;
                    float b0 = __ldg(qkv_b + col), b1 = __ldg(qkv_b + col + 1);
                    float v00 = acc[t][0]+b0, v01 = acc[t][1]+b1;
                    float v10 = acc[t][2]+b0, v11 = acc[t][3]+b1;
                    if (ctype == 0) { v00*=scale; v01*=scale; v10*=scale; v11*=scale; }
                    if (ctype < 2) {
                        if (r0 < NTOK)
                            *(uint32_t*)(smc + OFF_QK + r0*QKP + col*2) = packbf(v00, v01);
                        if (r1 < NTOK)
                            *(uint32_t*)(smc + OFF_QK + r1*QKP + col*2) = packbf(v10, v11);
                    } else {
                        const int vc = col - 256;       // V dim index
                        if (r0 < NTOK) {
                            __nv_bfloat16 h0 = __float2bfloat16(v00);
                            __nv_bfloat16 h1 = __float2bfloat16(v01);
                            *(__nv_bfloat16*)(smc + OFF_VT + vc*VTP + r0*2) = h0;
                            *(__nv_bfloat16*)(smc + OFF_VT + (vc+1)*VTP + r0*2) = h1;
                            *(__nv_bfloat16*)(smc + OFF_VT + VTLO_D + vc*VTP + r0*2) =
                                __float2bfloat16(v00 - __bfloat162float(h0));
                            *(__nv_bfloat16*)(smc + OFF_VT + VTLO_D + (vc+1)*VTP + r0*2) =
                                __float2bfloat16(v01 - __bfloat162float(h1));
                        }
                        if (r1 < NTOK) {
                            __nv_bfloat16 h0 = __float2bfloat16(v10);
                            __nv_bfloat16 h1 = __float2bfloat16(v11);
                            *(__nv_bfloat16*)(smc + OFF_VT + vc*VTP + r1*2) = h0;
                            *(__nv_bfloat16*)(smc + OFF_VT + (vc+1)*VTP + r1*2) = h1;
                            *(__nv_bfloat16*)(smc + OFF_VT + VTLO_D + vc*VTP + r1*2) =
                                __float2bfloat16(v10 - __bfloat162float(h0));
                            *(__nv_bfloat16*)(smc + OFF_VT + VTLO_D + (vc+1)*VTP + r1*2) =
                                __float2bfloat16(v11 - __bfloat162float(h1));
                        }
                    }
                }
            }
            __syncthreads();
        }
    }

    // ---------------- attention thread constants ----------------
    const float* maskb = mask + (size_t)(b % Lmask) * NTOK * NTOK;
    const int half = nh;                   // scores n-half / PV n-subtile
    const int nt = 4 - half;               // scores n-tiles: 4 or 3
    const uint32_t aQ = sb + OFF_QK + (uint32_t)arowA*QKP + cbA;
    uint32_t jbase[4];
    int bje[4][2], bjo[4][2];
    #pragma unroll
    for (int jj = 0; jj < 4; jj++) {
        const int nj = 2*jj + half;
        jbase[jj] = sb + OFF_QK + (uint32_t)min(nj*16 + rbB, NTOK-1)*QKP + 256 + cbB;
        #pragma unroll
        for (int t = 0; t < 2; t++) {
            const int ce = nj*16 + t*8 + tg*2;
            bje[jj][t] = airel(min(ce, NTOK-1));
            bjo[jj][t] = airel(min(ce+1, NTOK-1));
        }
    }
    const int ai0 = airel(min(r0, NTOK-1)), ai1 = airel(min(r1, NTOK-1));
    const uint32_t pA = sb + OFF_S + (uint32_t)(mi*16 + rbA)*SROW + cbA;   // Phi
    const uint32_t vB = sb + OFF_VT + (uint32_t)(half*16 + rbB)*VTP + cbB; // VThi

    // ---------------- per-head attention ----------------
    for (int h = 0; h < NHEADS; h++) {
        const float* relh = rel + h * 507;

        // --- scores: s = q_h k_h^T + bias + mask (bf16 MMA, fp32 acc) ---
        if (warp < 14) {
            uint32_t aq[2][4];
            ldsm4(aq[0], aQ + h*64);
            ldsm4(aq[1], aQ + h*64 + 32);
            float acc[4][2][4];
            #pragma unroll
            for (int jj = 0; jj < 4; jj++)
                #pragma unroll
                for (int t = 0; t < 2; t++)
                    #pragma unroll
                    for (int i = 0; i < 4; i++) acc[jj][t][i] = 0.f;
            #pragma unroll
            for (int jj = 0; jj < 4; jj++) if (jj < nt) {
                #pragma unroll
                for (int ks = 0; ks < 2; ks++) {
                    uint32_t kb[4];
                    ldsm4(kb, jbase[jj] + h*64 + ks*32);
                    mma16816(acc[jj][0], aq[ks], kb[0], kb[1]);
                    mma16816(acc[jj][1], aq[ks], kb[2], kb[3]);
                }
            }
            #pragma unroll
            for (int jj = 0; jj < 4; jj++) if (jj < nt) {
                const int nj = 2*jj + half;
                #pragma unroll
                for (int t = 0; t < 2; t++) {
                    const int ce = nj*16 + t*8 + tg*2, co = ce + 1;
                    if (r0 < NTOK) {
                        if (ce < NTOK)
                            s[r0*112 + ce] = acc[jj][t][0] + __ldg(&relh[ai0 - bje[jj][t] + 253])
                                           + __ldg(&maskb[r0*NTOK + ce]);
                        if (co < NTOK)
                            s[r0*112 + co] = acc[jj][t][1] + __ldg(&relh[ai0 - bjo[jj][t] + 253])
                                           + __ldg(&maskb[r0*NTOK + co]);
                    }
                    if (r1 < NTOK) {
                        if (ce < NTOK)
                            s[r1*112 + ce] = acc[jj][t][2] + __ldg(&relh[ai1 - bje[jj][t] + 253])
                                           + __ldg(&maskb[r1*NTOK + ce]);
                        if (co < NTOK)
                            s[r1*112 + co] = acc[jj][t][3] + __ldg(&relh[ai1 - bjo[jj][t] + 253])
                                           + __ldg(&maskb[r1*NTOK + co]);
                    }
                }
            }
        }
        __syncthreads();

        // --- softmax + in-place bf16 hi/lo conversion (row-exclusive) ---
        for (int row = warp; row < NTOK; row += 16) {
            float v0 = (lane      < NTOK) ? s[row*112 + lane     ] : -1e30f;
            float v1 = (lane + 32 < NTOK) ? s[row*112 + lane + 32] : -1e30f;
            float v2 = (lane + 64 < NTOK) ? s[row*112 + lane + 64] : -1e30f;
            float v3 = (lane + 96 < NTOK) ? s[row*112 + lane + 96] : -1e30f;
            float m = fmaxf(fmaxf(v0, v1), fmaxf(v2, v3));
            #pragma unroll
            for (int o = 16; o > 0; o >>= 1)
                m = fmaxf(m, __shfl_xor_sync(0xffffffffu, m, o));
            v0 = __expf(v0 - m); v1 = __expf(v1 - m);
            v2 = __expf(v2 - m); v3 = __expf(v3 - m);
            float sum = v0 + v1 + v2 + v3;
            #pragma unroll
            for (int o = 16; o > 0; o >>= 1)
                sum += __shfl_xor_sync(0xffffffffu, sum, o);
            const float inv = 1.0f / sum;
            const float pv[4] = {v0*inv, v1*inv, v2*inv, v3*inv};
            char* rowb = smc + OFF_S + row*SROW;
            #pragma unroll
            for (int g4 = 0; g4 < 4; g4++) {
                const int col = lane + 32*g4;
                if (col < NTOK) {
                    __nv_bfloat16 hi = __float2bfloat16(pv[g4]);
                    __nv_bfloat16 lo = __float2bfloat16(pv[g4] - __bfloat162float(hi));
                    *(__nv_bfloat16*)(rowb + col*2)       = hi;
                    *(__nv_bfloat16*)(rowb + 224 + col*2) = lo;
                } else if (col < 112) {                   // zero k-padding
                    *(__nv_bfloat16*)(rowb + col*2)       = __float2bfloat16(0.f);
                    *(__nv_bfloat16*)(rowb + 224 + col*2) = __float2bfloat16(0.f);
                }
            }
        }
        __syncthreads();

        // --- o_h = P V_h (3-term hi/lo MMA) -> Ohi/Olo ---
        if (warp < 14) {
            float acc[2][4] = {{0,0,0,0},{0,0,0,0}};
            #pragma unroll
            for (int ks = 0; ks < 7; ks++) {
                uint32_t ap[4], al[4], bh[4], bl[4];
                ldsm4(ap, pA + ks*32);
                ldsm4(al, pA + 224 + ks*32);
                ldsm4(bh, vB + h*7680 + ks*32);
                ldsm4(bl, vB + h*7680 + VTLO_D + ks*32);
                mma16816(acc[0], ap, bh[0], bh[1]);
                mma16816(acc[0], al, bh[0], bh[1]);
                mma16816(acc[0], ap, bl[0], bl[1]);
                mma16816(acc[1], ap, bh[2], bh[3]);
                mma16816(acc[1], al, bh[2], bh[3]);
                mma16816(acc[1], ap, bl[2], bl[3]);
            }
            #pragma unroll
            for (int t = 0; t < 2; t++) {
                const int col = h*32 + half*16 + t*8 + tg*2;
                if (r0 < NTOK) {
                    __nv_bfloat16 h0 = __float2bfloat16(acc[t][0]);
                    __nv_bfloat16 h1 = __float2bfloat16(acc[t][1]);
                    __nv_bfloat162 hp(h0, h1);
                    *(uint32_t*)(smc + OFF_O + r0*OP2 + col*2) = *(uint32_t*)&hp;
                    *(uint32_t*)(smc + OFF_OLO + r0*OP2 + col*2) =
                        packbf(acc[t][0] - __bfloat162float(h0),
                               acc[t][1] - __bfloat162float(h1));
                }
                if (r1 < NTOK) {
                    __nv_bfloat16 h0 = __float2bfloat16(acc[t][2]);
                    __nv_bfloat16 h1 = __float2bfloat16(acc[t][3]);
                    __nv_bfloat162 hp(h0, h1);
                    *(uint32_t*)(smc + OFF_O + r1*OP2 + col*2) = *(uint32_t*)&hp;
                    *(uint32_t*)(smc + OFF_OLO + r1*OP2 + col*2) =
                        packbf(acc[t][2] - __bfloat162float(h0),
                               acc[t][3] - __bfloat162float(h1));
                }
            }
        }
        __syncthreads();
    }

    // ---------------- output projection (tensor cores, 3-term) ----------------
    {
        uint32_t Ahi[8][4], Alo[8][4];
        if (warp < 14) {
            #pragma unroll
            for (int kk = 0; kk < 8; kk++) {
                ldsm4(Ahi[kk], sb + OFF_O   + aoff272 + kk*32);
                ldsm4(Alo[kk], sb + OFF_OLO + aoff272 + kk*32);
            }
        }
        float* outg = out + (size_t)b * NTOK * CDIM;
        for (int ch = 0; ch < 4; ch++) {
            const int c0 = ch * 32;
            for (int f = tid; f < 32*CDIM/4; f += NTHREADS) {
                int row = f >> 5, c4 = f & 31;
                float4 v = *(const float4*)(proj_w + (size_t)(c0 + row)*CDIM + c4*4);
                uint2 hi, lo; split4(v, hi, lo);
                *(uint2*)(smc + OFF_W   + row*OP2 + c4*8) = hi;
                *(uint2*)(smc + OFF_WLO + row*OP2 + c4*8) = lo;
            }
            __syncthreads();
            if (warp < 14) {
                float acc[2][4] = {{0,0,0,0},{0,0,0,0}};
                #pragma unroll
                for (int kk = 0; kk < 8; kk++) {
                    uint32_t bh[4], bl[4];
                    ldsm4(bh, sb + OFF_W   + boffW + kk*32);
                    ldsm4(bl, sb + OFF_WLO + boffW + kk*32);
                    mma16816(acc[0], Ahi[kk], bh[0], bh[1]);
                    mma16816(acc[0], Alo[kk], bh[0], bh[1]);
                    mma16816(acc[0], Ahi[kk], bl[0], bl[1]);
                    mma16816(acc[1], Ahi[kk], bh[2], bh[3]);
                    mma16816(acc[1], Alo[kk], bh[2], bh[3]);
                    mma16816(acc[1], Ahi[kk], bl[2], bl[3]);
                }
                #pragma unroll
                for (int t = 0; t < 2; t++) {
                    const int col = c0 + nh*16 + t*8 + tg*2;
                    float b0 = __ldg(proj_b + col), b1 = __ldg(proj_b + col + 1);
                    if (r0 < NTOK) {
                        float2 v; v.x = acc[t][0] + b0; v.y = acc[t][1] + b1;
                        *(float2*)&outg[r0*CDIM + col] = v;
                    }
                    if (r1 < NTOK) {
                        float2 v; v.x = acc[t][2] + b0; v.y = acc[t][3] + b1;
                        *(float2*)&outg[r1*CDIM + col] = v;
                    }
                }
            }
            __syncthreads();
        }
    }
}

extern "C" void kernel_launch(void* const* d_in, const int* in_sizes, int n_in,
                              void* d_out, int out_size)
{
    const float* x      = (const float*)d_in[0];
    const float* mask   = (const float*)d_in[1];
    const float* qkv_w  = (const float*)d_in[2];
    const float* qkv_b  = (const float*)d_in[3];
    const float* rel    = (const float*)d_in[4];
    const float* proj_w = (const float*)d_in[5];
    const float* proj_b = (const float*)d_in[6];

    const int B = in_sizes[0] / (NTOK * CDIM);          // 2048
    const int L = in_sizes[1] / (NTOK * NTOK);          // 512

    cudaFuncSetAttribute(wa3d_kernel,
                         cudaFuncAttributeMaxDynamicSharedMemorySize,
                         SMEM_BYTES);

    wa3d_kernel<<<B, NTHREADS, SMEM_BYTES>>>(x, mask, qkv_w, qkv_b, rel,
                                             proj_w, proj_b, (float*)d_out, L);
}

// round 9
// speedup vs baseline: 2.4545x; 1.5901x over previous
#include <cuda_runtime.h>
#include <cuda_bf16.h>
#include <stdint.h>

// WindowAttention3D fused kernel: one CTA per window, 512 threads (R8).
//   B=2048 windows, N=98 tokens, C=128 channels, H=4 heads, hd=32.
// R8: flash-style register-resident attention (scores+softmax+PV per warp,
//     no score SMEM, no attention syncs); weights pre-split to bf16 hi/lo in
//     gmem by a prep kernel; double-buffered weight staging.
// SMEM (bytes, total 201312):
//   [0     ) QKhi [98][264] bf16 (q cols 0..127 scaled | k cols 128..255)
//   [51744 ) VThi [128][120] bf16 (V transposed [dim][token]); VTlo at +30720
//   [113184) Ohi  [98][136] bf16 (also X input tile); Olo at 139840
//   [166496) W staging: 2 buffers x (hi 32 rows | lo 32 rows) x 272 B

#define NTOK 98
#define CDIM 128
#define NHEADS 4
#define NTHREADS 512
#define QKP 528
#define VTP 240
#define OP2 272
#define OFF_QK 0
#define OFF_VT 51744
#define VTLO_D 30720
#define OFF_O 113184
#define OFF_OLO 139840
#define OFF_WB 166496
#define WBSZ 17408
#define SMEM_BYTES 201312

__device__ __nv_bfloat16 g_qw_hi[384*128];
__device__ __nv_bfloat16 g_qw_lo[384*128];
__device__ __nv_bfloat16 g_pw_hi[128*128];
__device__ __nv_bfloat16 g_pw_lo[128*128];

__global__ void prep_kernel(const float* __restrict__ qkv_w,
                            const float* __restrict__ proj_w)
{
    int i = blockIdx.x*blockDim.x + threadIdx.x;
    if (i < 384*128) {
        float v = qkv_w[i];
        __nv_bfloat16 h = __float2bfloat16(v);
        g_qw_hi[i] = h;
        g_qw_lo[i] = __float2bfloat16(v - __bfloat162float(h));
    } else {
        int j = i - 384*128;
        if (j < 128*128) {
            float v = proj_w[j];
            __nv_bfloat16 h = __float2bfloat16(v);
            g_pw_hi[j] = h;
            g_pw_lo[j] = __float2bfloat16(v - __bfloat162float(h));
        }
    }
}

__device__ __forceinline__ uint32_t smem_u32(const void* p) {
    uint32_t a;
    asm("{ .reg .u64 t; cvta.to.shared.u64 t, %1; cvt.u32.u64 %0, t; }"
        : "=r"(a) : "l"(p));
    return a;
}
__device__ __forceinline__ void ldsm4(uint32_t* r, uint32_t a) {
    asm volatile("ldmatrix.sync.aligned.m8n8.x4.shared.b16 {%0,%1,%2,%3}, [%4];"
        : "=r"(r[0]), "=r"(r[1]), "=r"(r[2]), "=r"(r[3]) : "r"(a));
}
__device__ __forceinline__ void mma16816(float* c, const uint32_t* a,
                                         uint32_t b0, uint32_t b1) {
    asm volatile("mma.sync.aligned.m16n8k16.row.col.f32.bf16.bf16.f32 "
        "{%0,%1,%2,%3}, {%4,%5,%6,%7}, {%8,%9}, {%0,%1,%2,%3};"
        : "+f"(c[0]), "+f"(c[1]), "+f"(c[2]), "+f"(c[3])
        : "r"(a[0]), "r"(a[1]), "r"(a[2]), "r"(a[3]), "r"(b0), "r"(b1));
}
__device__ __forceinline__ uint32_t packbf(float a, float b) {
    __nv_bfloat162 t(__float2bfloat16(a), __float2bfloat16(b));
    return *(uint32_t*)&t;
}
__device__ __forceinline__ void packsplit(float a, float b,
                                          uint32_t& hi, uint32_t& lo) {
    __nv_bfloat16 ha = __float2bfloat16(a), hb = __float2bfloat16(b);
    __nv_bfloat162 hp(ha, hb);
    hi = *(uint32_t*)&hp;
    lo = packbf(a - __bfloat162float(ha), b - __bfloat162float(hb));
}
__device__ __forceinline__ void split4(float4 v, uint2& hi, uint2& lo) {
    uint32_t h0, l0, h1, l1;
    packsplit(v.x, v.y, h0, l0);
    packsplit(v.z, v.w, h1, l1);
    hi.x = h0; hi.y = h1; lo.x = l0; lo.y = l1;
}
__device__ __forceinline__ int airel(int i) {
    return (i/49)*169 + ((i/7)%7)*13 + (i%7);
}

__global__ __launch_bounds__(NTHREADS, 1)
void wa3d_kernel(const float* __restrict__ x,
                 const float* __restrict__ mask,
                 const float* __restrict__ qkv_b,
                 const float* __restrict__ rel,
                 const float* __restrict__ proj_b,
                 float* __restrict__ out,
                 int Lmask)
{
    extern __shared__ char smc[];
    const uint32_t sb = smem_u32(smc);

    const int tid  = threadIdx.x;
    const int warp = tid >> 5, lane = tid & 31;
    const int b = blockIdx.x;
    const float scale = 0.17677669529663688f;

    // warp-tile mapping (GEMM phases): warps 0..13 -> (m-tile mi, n-half nh)
    const int mi = warp >> 1, nh = warp & 1;
    const int g = lane >> 2, tg = lane & 3;
    const int r0g = mi*16 + g, r1g = r0g + 8;
    // A lane map: bit3 -> row+8, bit4 -> k-half
    const int rbA = (lane & 7) + ((lane >> 3) & 1)*8;
    const uint32_t cbA = ((lane >> 4) & 1)*16;
    const uint32_t aoff272 = (uint32_t)min(mi*16 + rbA, NTOK-1)*OP2 + cbA;
    // B lane map: bit4 -> n+8, bit3 -> k-half
    const int rbB = (lane & 7) + ((lane >> 4) & 1)*8;
    const uint32_t cbB = ((lane >> 3) & 1)*16;
    const uint32_t boffW = (uint32_t)((rbB + nh*16)*OP2) + cbB;

    // stage a 32-col weight chunk (bf16 hi/lo from gmem) into buffer buf
    auto stageW = [&](const __nv_bfloat16* hsrc, const __nv_bfloat16* lsrc,
                      int c0, int buf) {
        char* wb = smc + OFF_WB + buf*WBSZ;
        #pragma unroll
        for (int f0 = 0; f0 < 2; f0++) {
            int f = tid + f0*NTHREADS;
            int hl = f >> 9, r = (f >> 4) & 31, q = f & 15;
            const __nv_bfloat16* src = hl ? lsrc : hsrc;
            uint4 v = *(const uint4*)(src + (size_t)(c0 + r)*CDIM + q*8);
            *(uint4*)(wb + (hl*32 + r)*OP2 + q*16) = v;
        }
    };

    // ---------------- 1. x -> bf16 hi/lo (O region) + stage W chunk 0 ----------------
    {
        const float4* xb = (const float4*)(x + (size_t)b * NTOK * CDIM);
        for (int f = tid; f < NTOK*CDIM/4; f += NTHREADS) {
            int row = f >> 5, c4 = f & 31;
            uint2 hi, lo; split4(xb[f], hi, lo);
            *(uint2*)(smc + OFF_O   + row*OP2 + c4*8) = hi;
            *(uint2*)(smc + OFF_OLO + row*OP2 + c4*8) = lo;
        }
        stageW(g_qw_hi, g_qw_lo, 0, 0);
    }
    __syncthreads();

    // ---------------- 2. QKV projection (3-term MMA, double-buffered W) ----------------
    {
        uint32_t Ahi[8][4], Alo[8][4];
        if (warp < 14) {
            #pragma unroll
            for (int kk = 0; kk < 8; kk++) {
                ldsm4(Ahi[kk], sb + OFF_O   + aoff272 + kk*32);
                ldsm4(Alo[kk], sb + OFF_OLO + aoff272 + kk*32);
            }
        }
        for (int ch = 0; ch < 12; ch++) {
            if (ch < 11) stageW(g_qw_hi, g_qw_lo, 32*(ch+1), (ch+1)&1);
            if (warp < 14) {
                const uint32_t wb = sb + OFF_WB + (ch&1)*WBSZ;
                float acc[2][4] = {{0,0,0,0},{0,0,0,0}};
                #pragma unroll
                for (int kk = 0; kk < 8; kk++) {
                    uint32_t bh[4], bl[4];
                    ldsm4(bh, wb + boffW + kk*32);
                    ldsm4(bl, wb + 32*OP2 + boffW + kk*32);
                    mma16816(acc[0], Ahi[kk], bh[0], bh[1]);
                    mma16816(acc[0], Alo[kk], bh[0], bh[1]);
                    mma16816(acc[0], Ahi[kk], bl[0], bl[1]);
                    mma16816(acc[1], Ahi[kk], bh[2], bh[3]);
                    mma16816(acc[1], Alo[kk], bh[2], bh[3]);
                    mma16816(acc[1], Ahi[kk], bl[2], bl[3]);
                }
                const int c0 = ch*32;
                const int ctype = c0 >> 7;              // 0:q 1:k 2:v
                #pragma unroll
                for (int t = 0; t < 2; t++) {
                    const int col = c0 + nh*16 + t*8 + tg*2;
                    float b0 = __ldg(qkv_b + col), b1 = __ldg(qkv_b + col + 1);
                    float v00 = acc[t][0]+b0, v01 = acc[t][1]+b1;
                    float v10 = acc[t][2]+b0, v11 = acc[t][3]+b1;
                    if (ctype == 0) { v00*=scale; v01*=scale; v10*=scale; v11*=scale; }
                    if (ctype < 2) {
                        if (r0g < NTOK)
                            *(uint32_t*)(smc + OFF_QK + r0g*QKP + col*2) = packbf(v00, v01);
                        if (r1g < NTOK)
                            *(uint32_t*)(smc + OFF_QK + r1g*QKP + col*2) = packbf(v10, v11);
                    } else {
                        const int vc = col - 256;
                        if (r0g < NTOK) {
                            uint32_t h2, l2; packsplit(v00, v01, h2, l2);
                            __nv_bfloat162 hp = *(__nv_bfloat162*)&h2;
                            __nv_bfloat162 lp = *(__nv_bfloat162*)&l2;
                            *(__nv_bfloat16*)(smc + OFF_VT + vc*VTP + r0g*2) = hp.x;
                            *(__nv_bfloat16*)(smc + OFF_VT + (vc+1)*VTP + r0g*2) = hp.y;
                            *(__nv_bfloat16*)(smc + OFF_VT + VTLO_D + vc*VTP + r0g*2) = lp.x;
                            *(__nv_bfloat16*)(smc + OFF_VT + VTLO_D + (vc+1)*VTP + r0g*2) = lp.y;
                        }
                        if (r1g < NTOK) {
                            uint32_t h2, l2; packsplit(v10, v11, h2, l2);
                            __nv_bfloat162 hp = *(__nv_bfloat162*)&h2;
                            __nv_bfloat162 lp = *(__nv_bfloat162*)&l2;
                            *(__nv_bfloat16*)(smc + OFF_VT + vc*VTP + r1g*2) = hp.x;
                            *(__nv_bfloat16*)(smc + OFF_VT + (vc+1)*VTP + r1g*2) = hp.y;
                            *(__nv_bfloat16*)(smc + OFF_VT + VTLO_D + vc*VTP + r1g*2) = lp.x;
                            *(__nv_bfloat16*)(smc + OFF_VT + VTLO_D + (vc+1)*VTP + r1g*2) = lp.y;
                        }
                    }
                }
            }
            __syncthreads();
        }
    }

    // zero VT token padding (tokens 98..119, all 256 hi+lo rows) + stage proj chunk 0
    {
        for (int f = tid; f < 256*11; f += NTHREADS) {
            int rr = f / 11, q = f % 11;
            *(uint32_t*)(smc + OFF_VT + (rr >= 128 ? VTLO_D : 0)
                         + (rr & 127)*VTP + 196 + q*4) = 0u;
        }
        stageW(g_pw_hi, g_pw_lo, 0, 0);
    }
    __syncthreads();

    // ---------------- 3. flash attention: per-warp (head, m-tile) units ----------------
    const float* maskb = mask + (size_t)(b % Lmask) * NTOK * NTOK;
    #pragma unroll 1
    for (int it = 0; it < 2; it++) {
        const int u = warp + 16*it;
        if (u < 28) {
            const int h = u / 7, m4 = u % 7;
            const int r0 = m4*16 + g, r1 = r0 + 8;
            const int r0c = min(r0, NTOK-1), r1c = min(r1, NTOK-1);
            const int ai0 = airel(r0c), ai1 = airel(r1c);
            const float* relh = rel + h*507;

            // q A-fragments (k = 32 dims)
            uint32_t aq[2][4];
            const uint32_t aQ = sb + OFF_QK
                + (uint32_t)min(m4*16 + rbA, NTOK-1)*QKP + h*64 + cbA;
            ldsm4(aq[0], aQ);
            ldsm4(aq[1], aQ + 32);

            // scores: 16 x 112 strip in registers
            float acc[7][2][4];
            #pragma unroll
            for (int jj = 0; jj < 7; jj++) {
                #pragma unroll
                for (int t = 0; t < 2; t++)
                    #pragma unroll
                    for (int e = 0; e < 4; e++) acc[jj][t][e] = 0.f;
                const uint32_t kbase = sb + OFF_QK
                    + (uint32_t)min(jj*16 + rbB, NTOK-1)*QKP + 256 + h*64 + cbB;
                uint32_t kb[4];
                ldsm4(kb, kbase);
                mma16816(acc[jj][0], aq[0], kb[0], kb[1]);
                mma16816(acc[jj][1], aq[0], kb[2], kb[3]);
                ldsm4(kb, kbase + 32);
                mma16816(acc[jj][0], aq[1], kb[0], kb[1]);
                mma16816(acc[jj][1], aq[1], kb[2], kb[3]);
            }

            // bias + mask + masking of padded cols; row-max
            float mx0 = -1e30f, mx1 = -1e30f;
            #pragma unroll
            for (int jj = 0; jj < 7; jj++)
                #pragma unroll
                for (int t = 0; t < 2; t++) {
                    const int c = jj*16 + t*8 + tg*2;
                    if (c < NTOK) {
                        const int bc = airel(c);
                        acc[jj][t][0] += __ldg(relh + ai0 - bc + 253)
                                       + __ldg(maskb + r0c*NTOK + c);
                        acc[jj][t][2] += __ldg(relh + ai1 - bc + 253)
                                       + __ldg(maskb + r1c*NTOK + c);
                    } else { acc[jj][t][0] = -1e30f; acc[jj][t][2] = -1e30f; }
                    if (c + 1 < NTOK) {
                        const int bc = airel(c + 1);
                        acc[jj][t][1] += __ldg(relh + ai0 - bc + 253)
                                       + __ldg(maskb + r0c*NTOK + c + 1);
                        acc[jj][t][3] += __ldg(relh + ai1 - bc + 253)
                                       + __ldg(maskb + r1c*NTOK + c + 1);
                    } else { acc[jj][t][1] = -1e30f; acc[jj][t][3] = -1e30f; }
                    mx0 = fmaxf(mx0, fmaxf(acc[jj][t][0], acc[jj][t][1]));
                    mx1 = fmaxf(mx1, fmaxf(acc[jj][t][2], acc[jj][t][3]));
                }
            mx0 = fmaxf(mx0, __shfl_xor_sync(0xffffffffu, mx0, 1));
            mx0 = fmaxf(mx0, __shfl_xor_sync(0xffffffffu, mx0, 2));
            mx1 = fmaxf(mx1, __shfl_xor_sync(0xffffffffu, mx1, 1));
            mx1 = fmaxf(mx1, __shfl_xor_sync(0xffffffffu, mx1, 2));

            float s0 = 0.f, s1 = 0.f;
            #pragma unroll
            for (int jj = 0; jj < 7; jj++)
                #pragma unroll
                for (int t = 0; t < 2; t++) {
                    acc[jj][t][0] = __expf(acc[jj][t][0] - mx0);
                    acc[jj][t][1] = __expf(acc[jj][t][1] - mx0);
                    acc[jj][t][2] = __expf(acc[jj][t][2] - mx1);
                    acc[jj][t][3] = __expf(acc[jj][t][3] - mx1);
                    s0 += acc[jj][t][0] + acc[jj][t][1];
                    s1 += acc[jj][t][2] + acc[jj][t][3];
                }
            s0 += __shfl_xor_sync(0xffffffffu, s0, 1);
            s0 += __shfl_xor_sync(0xffffffffu, s0, 2);
            s1 += __shfl_xor_sync(0xffffffffu, s1, 1);
            s1 += __shfl_xor_sync(0xffffffffu, s1, 2);
            const float inv0 = 1.0f / s0, inv1 = 1.0f / s1;
            #pragma unroll
            for (int jj = 0; jj < 7; jj++)
                #pragma unroll
                for (int t = 0; t < 2; t++) {
                    acc[jj][t][0] *= inv0; acc[jj][t][1] *= inv0;
                    acc[jj][t][2] *= inv1; acc[jj][t][3] *= inv1;
                }

            // PV: P's C-fragment == A-fragment (n -> k), 3-term hi/lo
            float oacc[4][4];
            #pragma unroll
            for (int n8 = 0; n8 < 4; n8++)
                #pragma unroll
                for (int e = 0; e < 4; e++) oacc[n8][e] = 0.f;
            #pragma unroll
            for (int jj = 0; jj < 7; jj++) {
                uint32_t ap[4], al[4];
                packsplit(acc[jj][0][0], acc[jj][0][1], ap[0], al[0]);
                packsplit(acc[jj][0][2], acc[jj][0][3], ap[1], al[1]);
                packsplit(acc[jj][1][0], acc[jj][1][1], ap[2], al[2]);
                packsplit(acc[jj][1][2], acc[jj][1][3], ap[3], al[3]);
                #pragma unroll
                for (int n2 = 0; n2 < 2; n2++) {
                    const uint32_t vb = sb + OFF_VT
                        + (uint32_t)(h*32 + n2*16 + rbB)*VTP + jj*32 + cbB;
                    uint32_t bh[4], bl[4];
                    ldsm4(bh, vb);
                    ldsm4(bl, vb + VTLO_D);
                    mma16816(oacc[n2*2+0], ap, bh[0], bh[1]);
                    mma16816(oacc[n2*2+0], al, bh[0], bh[1]);
                    mma16816(oacc[n2*2+0], ap, bl[0], bl[1]);
                    mma16816(oacc[n2*2+1], ap, bh[2], bh[3]);
                    mma16816(oacc[n2*2+1], al, bh[2], bh[3]);
                    mma16816(oacc[n2*2+1], ap, bl[2], bl[3]);
                }
            }
            // write O hi/lo
            #pragma unroll
            for (int n8 = 0; n8 < 4; n8++) {
                const int col = h*32 + n8*8 + tg*2;
                if (r0 < NTOK) {
                    uint32_t hi, lo;
                    packsplit(oacc[n8][0], oacc[n8][1], hi, lo);
                    *(uint32_t*)(smc + OFF_O   + r0*OP2 + col*2) = hi;
                    *(uint32_t*)(smc + OFF_OLO + r0*OP2 + col*2) = lo;
                }
                if (r1 < NTOK) {
                    uint32_t hi, lo;
                    packsplit(oacc[n8][2], oacc[n8][3], hi, lo);
                    *(uint32_t*)(smc + OFF_O   + r1*OP2 + col*2) = hi;
                    *(uint32_t*)(smc + OFF_OLO + r1*OP2 + col*2) = lo;
                }
            }
        }
    }
    __syncthreads();

    // ---------------- 4. output projection (3-term MMA, double-buffered) ----------------
    {
        uint32_t Ahi[8][4], Alo[8][4];
        if (warp < 14) {
            #pragma unroll
            for (int kk = 0; kk < 8; kk++) {
                ldsm4(Ahi[kk], sb + OFF_O   + aoff272 + kk*32);
                ldsm4(Alo[kk], sb + OFF_OLO + aoff272 + kk*32);
            }
        }
        float* outg = out + (size_t)b * NTOK * CDIM;
        for (int ch = 0; ch < 4; ch++) {
            if (ch < 3) stageW(g_pw_hi, g_pw_lo, 32*(ch+1), (ch+1)&1);
            if (warp < 14) {
                const uint32_t wb = sb + OFF_WB + (ch&1)*WBSZ;
                float acc[2][4] = {{0,0,0,0},{0,0,0,0}};
                #pragma unroll
                for (int kk = 0; kk < 8; kk++) {
                    uint32_t bh[4], bl[4];
                    ldsm4(bh, wb + boffW + kk*32);
                    ldsm4(bl, wb + 32*OP2 + boffW + kk*32);
                    mma16816(acc[0], Ahi[kk], bh[0], bh[1]);
                    mma16816(acc[0], Alo[kk], bh[0], bh[1]);
                    mma16816(acc[0], Ahi[kk], bl[0], bl[1]);
                    mma16816(acc[1], Ahi[kk], bh[2], bh[3]);
                    mma16816(acc[1], Alo[kk], bh[2], bh[3]);
                    mma16816(acc[1], Ahi[kk], bl[2], bl[3]);
                }
                #pragma unroll
                for (int t = 0; t < 2; t++) {
                    const int col = ch*32 + nh*16 + t*8 + tg*2;
                    float b0 = __ldg(proj_b + col), b1 = __ldg(proj_b + col + 1);
                    if (r0g < NTOK) {
                        float2 v; v.x = acc[t][0] + b0; v.y = acc[t][1] + b1;
                        *(float2*)&outg[r0g*CDIM + col] = v;
                    }
                    if (r1g < NTOK) {
                        float2 v; v.x = acc[t][2] + b0; v.y = acc[t][3] + b1;
                        *(float2*)&outg[r1g*CDIM + col] = v;
                    }
                }
            }
            __syncthreads();
        }
    }
}

extern "C" void kernel_launch(void* const* d_in, const int* in_sizes, int n_in,
                              void* d_out, int out_size)
{
    const float* x      = (const float*)d_in[0];
    const float* mask   = (const float*)d_in[1];
    const float* qkv_w  = (const float*)d_in[2];
    const float* qkv_b  = (const float*)d_in[3];
    const float* rel    = (const float*)d_in[4];
    const float* proj_w = (const float*)d_in[5];
    const float* proj_b = (const float*)d_in[6];

    const int B = in_sizes[0] / (NTOK * CDIM);          // 2048
    const int L = in_sizes[1] / (NTOK * NTOK);          // 512

    prep_kernel<<<256, 256>>>(qkv_w, proj_w);

    cudaFuncSetAttribute(wa3d_kernel,
                         cudaFuncAttributeMaxDynamicSharedMemorySize,
                         SMEM_BYTES);
    wa3d_kernel<<<B, NTHREADS, SMEM_BYTES>>>(x, mask, qkv_b, rel,
                                             proj_b, (float*)d_out, L);
}